// round 8
// baseline (speedup 1.0000x reference)
#include <cuda_runtime.h>
#include <cuda_bf16.h>
#include <math.h>

#define DIM     4096
#define NHEADS  32
#define HD      128
#define BSZ     8
#define SEQ     512
#define START_P 512
#define KVLEN   1024
#define NTOK    (BSZ*SEQ)   /* 4096 tokens */
#define MAXSEQ  2048

// Scratch (device globals; no runtime allocation allowed)
__device__ float g_q[(size_t)NTOK * DIM];
__device__ float g_k[(size_t)NTOK * DIM];
__device__ float g_v[(size_t)NTOK * DIM];
__device__ float g_attn[(size_t)NTOK * DIM];
// tf32-pre-rounded operands
__device__ float g_xr[(size_t)NTOK * DIM];
__device__ float g_wqr[(size_t)DIM * DIM];
__device__ float g_wkr[(size_t)DIM * DIM];
__device__ float g_wvr[(size_t)DIM * DIM];
__device__ float g_wor[(size_t)DIM * DIM];
// merged + tf32-rounded K/V for attention, and router additive mask
__device__ float g_kc[(size_t)BSZ * NHEADS * KVLEN * HD];
__device__ float g_vc[(size_t)BSZ * NHEADS * KVLEN * HD];
__device__ float g_radd[(size_t)BSZ * KVLEN];

// ---------------------------------------------------------------------------
// TF32 / async helpers
// ---------------------------------------------------------------------------
__device__ __forceinline__ float tf32r(float x) {
    float y;
    asm("cvt.rna.tf32.f32 %0, %1;" : "=f"(y) : "f"(x));
    return y;
}

__device__ __forceinline__ void mma_tf32(float* c, const unsigned* a, const unsigned* b) {
    asm volatile(
        "mma.sync.aligned.m16n8k8.row.col.f32.tf32.tf32.f32 "
        "{%0,%1,%2,%3}, {%4,%5,%6,%7}, {%8,%9}, {%0,%1,%2,%3};"
        : "+f"(c[0]), "+f"(c[1]), "+f"(c[2]), "+f"(c[3])
        : "r"(a[0]), "r"(a[1]), "r"(a[2]), "r"(a[3]),
          "r"(b[0]), "r"(b[1]));
}

__device__ __forceinline__ void cp_async16(float* smem_dst, const float* gsrc) {
    unsigned saddr = (unsigned)__cvta_generic_to_shared(smem_dst);
    asm volatile("cp.async.cg.shared.global [%0], [%1], 16;\n"
                 :: "r"(saddr), "l"(gsrc));
}
#define CP_COMMIT() asm volatile("cp.async.commit_group;\n" ::: "memory")
#define CP_WAIT1()  asm volatile("cp.async.wait_group 1;\n" ::: "memory")

// ---------------------------------------------------------------------------
// Pre-round x and 4 weight matrices to tf32 (all are 4096x4096 fp32).
// ---------------------------------------------------------------------------
__global__ void round5_kernel(
    const float4* __restrict__ x,  const float4* __restrict__ wq,
    const float4* __restrict__ wk, const float4* __restrict__ wv,
    const float4* __restrict__ wo,
    float4* __restrict__ xr,  float4* __restrict__ wqr,
    float4* __restrict__ wkr, float4* __restrict__ wvr,
    float4* __restrict__ wor)
{
    size_t i = (size_t)blockIdx.x * blockDim.x + threadIdx.x;
    const size_t n = (size_t)DIM * DIM / 4;
    if (i >= n) return;
#define R4(dst, src) { float4 v = src[i]; \
    v.x = tf32r(v.x); v.y = tf32r(v.y); v.z = tf32r(v.z); v.w = tf32r(v.w); \
    dst[i] = v; }
    R4(xr, x) R4(wqr, wq) R4(wkr, wk) R4(wvr, wv) R4(wor, wo)
#undef R4
}

// ---------------------------------------------------------------------------
// TF32 tensor-core GEMM NT with cp.async 3-stage pipeline (unchanged).
// ---------------------------------------------------------------------------
#define GEMM_NSTAGE 3
#define GEMM_STAGE_FLOATS (2 * 128 * 32)
#define GEMM_SMEM_BYTES (GEMM_NSTAGE * GEMM_STAGE_FLOATS * 4)  /* 96 KB */

__global__ __launch_bounds__(256, 2) void sgemm_tf32_pipe(
    const float* __restrict__ A, const float* __restrict__ B,
    float* __restrict__ C, int M, int N, int K)
{
    extern __shared__ float sm[];
    const int tid = threadIdx.x;
    const int bm = blockIdx.y * 128;
    const int bn = blockIdx.x * 128;
    const int warp = tid >> 5, lane = tid & 31;
    const int wm = warp >> 2;
    const int wn = warp & 3;
    const int grp = lane >> 2;
    const int t4 = lane & 3;

    int pr[4], pc[4], poff[4];
#pragma unroll
    for (int p = 0; p < 4; p++) {
        int ci = tid + 256 * p;
        pr[p] = ci >> 3;
        pc[p] = ci & 7;
        poff[p] = (pr[p] << 5) + ((pc[p] ^ (pr[p] & 7)) << 2);
    }

    float acc[4][4][4];
#pragma unroll
    for (int mf = 0; mf < 4; mf++)
#pragma unroll
        for (int nf = 0; nf < 4; nf++)
#pragma unroll
            for (int r = 0; r < 4; r++) acc[mf][nf][r] = 0.f;

    const int KT = K / 32;

#pragma unroll
    for (int s = 0; s < 2; s++) {
        float* As = sm + s * GEMM_STAGE_FLOATS;
        float* Bs = As + 128 * 32;
        int k0 = s * 32;
#pragma unroll
        for (int p = 0; p < 4; p++) {
            cp_async16(As + poff[p], A + (size_t)(bm + pr[p]) * K + k0 + pc[p] * 4);
            cp_async16(Bs + poff[p], B + (size_t)(bn + pr[p]) * K + k0 + pc[p] * 4);
        }
        CP_COMMIT();
    }

    for (int kt = 0; kt < KT; kt++) {
        CP_WAIT1();
        __syncthreads();

        if (kt + 2 < KT) {
            int s = (kt + 2) % GEMM_NSTAGE;
            float* As = sm + s * GEMM_STAGE_FLOATS;
            float* Bs = As + 128 * 32;
            int k0 = (kt + 2) * 32;
#pragma unroll
            for (int p = 0; p < 4; p++) {
                cp_async16(As + poff[p], A + (size_t)(bm + pr[p]) * K + k0 + pc[p] * 4);
                cp_async16(Bs + poff[p], B + (size_t)(bn + pr[p]) * K + k0 + pc[p] * 4);
            }
        }
        CP_COMMIT();

        const float* As = sm + (kt % GEMM_NSTAGE) * GEMM_STAGE_FLOATS;
        const float* Bs = As + 128 * 32;

#pragma unroll
        for (int ks = 0; ks < 4; ks++) {
            const int ca = (2 * ks) ^ grp;
            const int cb = (2 * ks + 1) ^ grp;
            unsigned af[4][4], bf[4][2];
#pragma unroll
            for (int mf = 0; mf < 4; mf++) {
                int m0 = wm * 64 + mf * 16 + grp;
                af[mf][0] = __float_as_uint(As[m0 * 32 + ca * 4 + t4]);
                af[mf][1] = __float_as_uint(As[(m0 + 8) * 32 + ca * 4 + t4]);
                af[mf][2] = __float_as_uint(As[m0 * 32 + cb * 4 + t4]);
                af[mf][3] = __float_as_uint(As[(m0 + 8) * 32 + cb * 4 + t4]);
            }
#pragma unroll
            for (int nf = 0; nf < 4; nf++) {
                int n0 = wn * 32 + nf * 8 + grp;
                bf[nf][0] = __float_as_uint(Bs[n0 * 32 + ca * 4 + t4]);
                bf[nf][1] = __float_as_uint(Bs[n0 * 32 + cb * 4 + t4]);
            }
#pragma unroll
            for (int mf = 0; mf < 4; mf++)
#pragma unroll
                for (int nf = 0; nf < 4; nf++)
                    mma_tf32(acc[mf][nf], af[mf], bf[nf]);
        }
        __syncthreads();
    }

#pragma unroll
    for (int mf = 0; mf < 4; mf++) {
        int row0 = bm + wm * 64 + mf * 16 + grp;
#pragma unroll
        for (int nf = 0; nf < 4; nf++) {
            int col0 = bn + wn * 32 + nf * 8 + t4 * 2;
            float2 v0 = make_float2(acc[mf][nf][0], acc[mf][nf][1]);
            float2 v1 = make_float2(acc[mf][nf][2], acc[mf][nf][3]);
            *(float2*)(C + (size_t)row0 * N + col0) = v0;
            *(float2*)(C + (size_t)(row0 + 8) * N + col0) = v1;
        }
    }
}

// ---------------------------------------------------------------------------
// RoPE + scale + tf32-round Q in place. One thread per (token, head, i<64).
// ---------------------------------------------------------------------------
__global__ void rope_q_kernel(float* __restrict__ q)
{
    int idx = blockIdx.x * blockDim.x + threadIdx.x;
    const int total = NTOK * NHEADS * 64;
    if (idx >= total) return;
    int i   = idx & 63;
    int rest = idx >> 6;
    int h   = rest & (NHEADS - 1);
    int tok = rest >> 5;
    int s   = tok & (SEQ - 1);
    float pos = (float)(START_P + s);
    const float scale = 0.08838834764831845f;

    float freq = exp2f(-(float)i * 0.20762050593045702f);
    float ang = pos * freq;
    float c = cosf(ang), sn = sinf(ang);

    size_t base = (size_t)tok * DIM + h * HD + i;
    float q0 = q[base], q1 = q[base + 64];
    q[base]      = tf32r((q0 * c - q1 * sn) * scale);
    q[base + 64] = tf32r((q1 * c + q0 * sn) * scale);
}

// ---------------------------------------------------------------------------
// Build merged tf32 K'/V' [b][h][1024][128] (cache for pos<512; RoPE'd fresh
// K / fresh V for pos>=512) and the per-batch router additive mask.
// One thread per (b,h,pos,i<64) handling the (i, i+64) pair.
// ---------------------------------------------------------------------------
__global__ void prep_kv_kernel(
    const float* __restrict__ knew, const float* __restrict__ vnew,
    const float* __restrict__ cache_k, const float* __restrict__ cache_v,
    const float* __restrict__ router,
    float* __restrict__ kc, float* __restrict__ vc, float* __restrict__ radd)
{
    int idx = blockIdx.x * blockDim.x + threadIdx.x;
    const int total = BSZ * NHEADS * KVLEN * 64;
    if (idx >= total) return;
    int i   = idx & 63;
    int pos = (idx >> 6) & (KVLEN - 1);
    int h   = (idx >> 16) & (NHEADS - 1);
    int b   = idx >> 21;

    size_t dst = (((size_t)(b * NHEADS + h)) * KVLEN + pos) * HD + i;
    if (pos < START_P) {
        size_t src = (((size_t)(b * NHEADS + h)) * MAXSEQ + pos) * HD + i;
        kc[dst]      = tf32r(cache_k[src]);
        kc[dst + 64] = tf32r(cache_k[src + 64]);
        vc[dst]      = tf32r(cache_v[src]);
        vc[dst + 64] = tf32r(cache_v[src + 64]);
    } else {
        int s = pos - START_P;
        size_t src = ((size_t)(b * SEQ + s)) * DIM + h * HD + i;
        float freq = exp2f(-(float)i * 0.20762050593045702f);
        float ang = (float)pos * freq;
        float c = cosf(ang), sn = sinf(ang);
        float k0 = knew[src], k1 = knew[src + 64];
        kc[dst]      = tf32r(k0 * c - k1 * sn);
        kc[dst + 64] = tf32r(k1 * c + k0 * sn);
        vc[dst]      = tf32r(vnew[src]);
        vc[dst + 64] = tf32r(vnew[src + 64]);
    }
    if (h == 0 && i == 0) {
        float add = 0.f;
        if (pos >= START_P &&
            router[((size_t)b * SEQ + (pos - START_P)) * 2] == 0.f) add = -1e9f;
        radd[(size_t)b * KVLEN + pos] = add;
    }
}

// ---------------------------------------------------------------------------
// Tensor-core flash attention v2: cp.async double-buffered K/V pipeline.
// Block = 128 q rows x (h,b). 8 warps; warp = 16 q rows x 64-col KV tile.
// Q/K stride 132 (banks 4*grp+t4: conflict-free), V stride 136 (banks
// 8*t4+grp: conflict-free). All operands pre-tf32-rounded; no branches in
// the hot loop. Router mask preloaded for all 16 tiles.
// Smem: Q 128x132 | K0,K1 64x132 | V0,V1 64x136 | radd 1024  = 204 KB.
// ---------------------------------------------------------------------------
#define AQ_ST  132
#define AK_ST  132
#define AV_ST  136
#define AQ_FLOATS   (128 * AQ_ST)          /* 16896 */
#define AK_FLOATS   (64 * AK_ST)           /* 8448  */
#define AV_FLOATS   (64 * AV_ST)           /* 8704  */
#define ATTN_SMEM_FLOATS (AQ_FLOATS + 2*AK_FLOATS + 2*AV_FLOATS + KVLEN)

__global__ __launch_bounds__(256) void attn_tc2_kernel(
    const float* __restrict__ qp, const float* __restrict__ kc,
    const float* __restrict__ vc, const float* __restrict__ radd_g,
    float* __restrict__ out)
{
    extern __shared__ float smem[];
    float* Qs  = smem;
    float* K0s = smem + AQ_FLOATS;
    float* K1s = K0s + AK_FLOATS;
    float* V0s = K1s + AK_FLOATS;
    float* V1s = V0s + AV_FLOATS;
    float* radd_s = V1s + AV_FLOATS;   // [1024]

    const int qt = blockIdx.x;   // 0..3
    const int h  = blockIdx.y;
    const int b  = blockIdx.z;
    const int tid = threadIdx.x;
    const int wid = tid >> 5;
    const int lane = tid & 31;
    const int grp = lane >> 2;
    const int t4 = lane & 3;

    const float* qbase = qp + (size_t)(b * SEQ + qt * 128) * DIM + h * HD;
    const float* kbase = kc + ((size_t)(b * NHEADS + h)) * KVLEN * HD;
    const float* vbase = vc + ((size_t)(b * NHEADS + h)) * KVLEN * HD;

    // ---- G0: Q + radd + K0 + V0 ----
#pragma unroll
    for (int p = 0; p < 16; p++) {
        int ci = tid + 256 * p;
        int r = ci >> 5, c = ci & 31;
        cp_async16(Qs + r * AQ_ST + c * 4, qbase + (size_t)r * DIM + c * 4);
    }
    cp_async16(radd_s + tid * 4, radd_g + (size_t)b * KVLEN + tid * 4);
#pragma unroll
    for (int p = 0; p < 8; p++) {
        int ci = tid + 256 * p;
        int r = ci >> 5, c = ci & 31;
        cp_async16(K0s + r * AK_ST + c * 4, kbase + (size_t)r * HD + c * 4);
        cp_async16(V0s + r * AV_ST + c * 4, vbase + (size_t)r * HD + c * 4);
    }
    CP_COMMIT();
    // ---- G1: K1 + V1 ----
#pragma unroll
    for (int p = 0; p < 8; p++) {
        int ci = tid + 256 * p;
        int r = ci >> 5, c = ci & 31;
        cp_async16(K1s + r * AK_ST + c * 4, kbase + (size_t)(64 + r) * HD + c * 4);
        cp_async16(V1s + r * AV_ST + c * 4, vbase + (size_t)(64 + r) * HD + c * 4);
    }
    CP_COMMIT();

    float Oc[16][4];
#pragma unroll
    for (int nf = 0; nf < 16; nf++)
#pragma unroll
        for (int r = 0; r < 4; r++) Oc[nf][r] = 0.f;

    float mrun0 = -1e30f, mrun1 = -1e30f, lrun0 = 0.f, lrun1 = 0.f;
    const int m0 = wid * 16;
    const int qpos0 = START_P + qt * 128 + m0 + grp;
    const int qpos1 = qpos0 + 8;

    for (int kt = 0; kt < KVLEN / 64; kt++) {
        CP_WAIT1();
        __syncthreads();
        const float* Ks = (kt & 1) ? K1s : K0s;
        const float* Vs = (kt & 1) ? V1s : V0s;

        // ---- S = Q K^T ----
        float sc[8][4];
#pragma unroll
        for (int nf = 0; nf < 8; nf++)
#pragma unroll
            for (int r = 0; r < 4; r++) sc[nf][r] = 0.f;

#pragma unroll
        for (int ks = 0; ks < 16; ks++) {
            int ko = ks * 8;
            unsigned a[4];
            a[0] = __float_as_uint(Qs[(m0 + grp) * AQ_ST + ko + t4]);
            a[1] = __float_as_uint(Qs[(m0 + grp + 8) * AQ_ST + ko + t4]);
            a[2] = __float_as_uint(Qs[(m0 + grp) * AQ_ST + ko + t4 + 4]);
            a[3] = __float_as_uint(Qs[(m0 + grp + 8) * AQ_ST + ko + t4 + 4]);
#pragma unroll
            for (int nf = 0; nf < 8; nf++) {
                unsigned bb[2];
                bb[0] = __float_as_uint(Ks[(8 * nf + grp) * AK_ST + ko + t4]);
                bb[1] = __float_as_uint(Ks[(8 * nf + grp) * AK_ST + ko + t4 + 4]);
                mma_tf32(sc[nf], a, bb);
            }
        }

        // ---- mask + online softmax ----
        float rmax0 = -1e30f, rmax1 = -1e30f;
#pragma unroll
        for (int nf = 0; nf < 8; nf++) {
#pragma unroll
            for (int e = 0; e < 2; e++) {
                int col = 8 * nf + 2 * t4 + e;
                int ng = kt * 64 + col;
                float add = radd_s[kt * 64 + col];
                float v0 = sc[nf][e]     + add + ((ng > qpos0) ? -1e9f : 0.f);
                float v1 = sc[nf][2 + e] + add + ((ng > qpos1) ? -1e9f : 0.f);
                sc[nf][e] = v0; sc[nf][2 + e] = v1;
                rmax0 = fmaxf(rmax0, v0);
                rmax1 = fmaxf(rmax1, v1);
            }
        }
        rmax0 = fmaxf(rmax0, __shfl_xor_sync(0xffffffffu, rmax0, 1));
        rmax0 = fmaxf(rmax0, __shfl_xor_sync(0xffffffffu, rmax0, 2));
        rmax1 = fmaxf(rmax1, __shfl_xor_sync(0xffffffffu, rmax1, 1));
        rmax1 = fmaxf(rmax1, __shfl_xor_sync(0xffffffffu, rmax1, 2));

        float mnew0 = fmaxf(mrun0, rmax0);
        float mnew1 = fmaxf(mrun1, rmax1);
        float alpha0 = __expf(mrun0 - mnew0);
        float alpha1 = __expf(mrun1 - mnew1);
        mrun0 = mnew0; mrun1 = mnew1;

        float ps0 = 0.f, ps1 = 0.f;
#pragma unroll
        for (int nf = 0; nf < 8; nf++) {
#pragma unroll
            for (int e = 0; e < 2; e++) {
                float p0 = __expf(sc[nf][e] - mnew0);
                float p1 = __expf(sc[nf][2 + e] - mnew1);
                ps0 += p0; ps1 += p1;
                sc[nf][e] = tf32r(p0);
                sc[nf][2 + e] = tf32r(p1);
            }
        }
        ps0 += __shfl_xor_sync(0xffffffffu, ps0, 1);
        ps0 += __shfl_xor_sync(0xffffffffu, ps0, 2);
        ps1 += __shfl_xor_sync(0xffffffffu, ps1, 1);
        ps1 += __shfl_xor_sync(0xffffffffu, ps1, 2);
        lrun0 = lrun0 * alpha0 + ps0;
        lrun1 = lrun1 * alpha1 + ps1;

#pragma unroll
        for (int nf = 0; nf < 16; nf++) {
            Oc[nf][0] *= alpha0; Oc[nf][1] *= alpha0;
            Oc[nf][2] *= alpha1; Oc[nf][3] *= alpha1;
        }

        // ---- O += P V ----
        const int srcA = (lane & ~3) | (t4 >> 1);
        const int srcB = srcA + 2;
#pragma unroll
        for (int kcc = 0; kcc < 8; kcc++) {
            float x0 = __shfl_sync(0xffffffffu, sc[kcc][0], srcA);
            float x1 = __shfl_sync(0xffffffffu, sc[kcc][1], srcA);
            float y0 = __shfl_sync(0xffffffffu, sc[kcc][2], srcA);
            float y1 = __shfl_sync(0xffffffffu, sc[kcc][3], srcA);
            float x0b = __shfl_sync(0xffffffffu, sc[kcc][0], srcB);
            float x1b = __shfl_sync(0xffffffffu, sc[kcc][1], srcB);
            float y0b = __shfl_sync(0xffffffffu, sc[kcc][2], srcB);
            float y1b = __shfl_sync(0xffffffffu, sc[kcc][3], srcB);
            unsigned a[4];
            bool oddc = (t4 & 1);
            a[0] = __float_as_uint(oddc ? x1 : x0);
            a[1] = __float_as_uint(oddc ? y1 : y0);
            a[2] = __float_as_uint(oddc ? x1b : x0b);
            a[3] = __float_as_uint(oddc ? y1b : y0b);
            int ko = kcc * 8;
#pragma unroll
            for (int nf = 0; nf < 16; nf++) {
                unsigned bb[2];
                bb[0] = __float_as_uint(Vs[(ko + t4) * AV_ST + 8 * nf + grp]);
                bb[1] = __float_as_uint(Vs[(ko + t4 + 4) * AV_ST + 8 * nf + grp]);
                mma_tf32(Oc[nf], a, bb);
            }
        }
        __syncthreads();   // buffer reads done

        // ---- issue tile kt+2 into the buffers just freed ----
        if (kt + 2 < KVLEN / 64) {
            float* Kd = (kt & 1) ? K1s : K0s;
            float* Vd = (kt & 1) ? V1s : V0s;
            int row0 = (kt + 2) * 64;
#pragma unroll
            for (int p = 0; p < 8; p++) {
                int ci = tid + 256 * p;
                int r = ci >> 5, c = ci & 31;
                cp_async16(Kd + r * AK_ST + c * 4, kbase + (size_t)(row0 + r) * HD + c * 4);
                cp_async16(Vd + r * AV_ST + c * 4, vbase + (size_t)(row0 + r) * HD + c * 4);
            }
        }
        CP_COMMIT();
    }

    // ---- normalize + store (tf32-rounded: feeds WO GEMM) ----
    float inv0 = 1.f / lrun0;
    float inv1 = 1.f / lrun1;
    int tok0 = b * SEQ + qt * 128 + m0 + grp;
#pragma unroll
    for (int nf = 0; nf < 16; nf++) {
        int col = h * HD + 8 * nf + 2 * t4;
        float2 v0 = make_float2(tf32r(Oc[nf][0] * inv0), tf32r(Oc[nf][1] * inv0));
        float2 v1 = make_float2(tf32r(Oc[nf][2] * inv1), tf32r(Oc[nf][3] * inv1));
        *(float2*)(out + (size_t)tok0 * DIM + col) = v0;
        *(float2*)(out + (size_t)(tok0 + 8) * DIM + col) = v1;
    }
}

// ---------------------------------------------------------------------------
extern "C" void kernel_launch(void* const* d_in, const int* in_sizes, int n_in,
                              void* d_out, int out_size)
{
    const float* x       = (const float*)d_in[0];
    const float* router  = (const float*)d_in[1];
    const float* cache_k = (const float*)d_in[2];
    const float* cache_v = (const float*)d_in[3];
    const float* wq      = (const float*)d_in[6];
    const float* wk      = (const float*)d_in[7];
    const float* wv      = (const float*)d_in[8];
    const float* wo      = (const float*)d_in[9];
    float* out = (float*)d_out;

    float *qp, *kp, *vp, *ap, *xr, *wqr, *wkr, *wvr, *wor, *kcp, *vcp, *rap;
    cudaGetSymbolAddress((void**)&qp, g_q);
    cudaGetSymbolAddress((void**)&kp, g_k);
    cudaGetSymbolAddress((void**)&vp, g_v);
    cudaGetSymbolAddress((void**)&ap, g_attn);
    cudaGetSymbolAddress((void**)&xr, g_xr);
    cudaGetSymbolAddress((void**)&wqr, g_wqr);
    cudaGetSymbolAddress((void**)&wkr, g_wkr);
    cudaGetSymbolAddress((void**)&wvr, g_wvr);
    cudaGetSymbolAddress((void**)&wor, g_wor);
    cudaGetSymbolAddress((void**)&kcp, g_kc);
    cudaGetSymbolAddress((void**)&vcp, g_vc);
    cudaGetSymbolAddress((void**)&rap, g_radd);

    const int attn_smem = ATTN_SMEM_FLOATS * sizeof(float);   // ~204 KB
    cudaFuncSetAttribute(attn_tc2_kernel, cudaFuncAttributeMaxDynamicSharedMemorySize,
                         attn_smem);
    cudaFuncSetAttribute(sgemm_tf32_pipe, cudaFuncAttributeMaxDynamicSharedMemorySize,
                         GEMM_SMEM_BYTES);

    // pre-round x + weights to tf32
    {
        size_t n4 = (size_t)DIM * DIM / 4;
        int blocks = (int)((n4 + 255) / 256);
        round5_kernel<<<blocks, 256>>>(
            (const float4*)x, (const float4*)wq, (const float4*)wk,
            (const float4*)wv, (const float4*)wo,
            (float4*)xr, (float4*)wqr, (float4*)wkr, (float4*)wvr, (float4*)wor);
    }

    dim3 gg(DIM / 128, NTOK / 128), gt(256);
    sgemm_tf32_pipe<<<gg, gt, GEMM_SMEM_BYTES>>>(xr, wqr, qp, NTOK, DIM, DIM);
    sgemm_tf32_pipe<<<gg, gt, GEMM_SMEM_BYTES>>>(xr, wkr, kp, NTOK, DIM, DIM);
    sgemm_tf32_pipe<<<gg, gt, GEMM_SMEM_BYTES>>>(xr, wvr, vp, NTOK, DIM, DIM);

    // Q: rope+scale+tf32 in place
    {
        int total = NTOK * NHEADS * 64;
        rope_q_kernel<<<(total + 255) / 256, 256>>>(qp);
    }
    // K'/V' merge + rope + tf32, router mask
    {
        int total = BSZ * NHEADS * KVLEN * 64;
        prep_kv_kernel<<<(total + 255) / 256, 256>>>(
            kp, vp, cache_k, cache_v, router, kcp, vcp, rap);
    }

    {
        dim3 grid(SEQ / 128, NHEADS, BSZ);
        attn_tc2_kernel<<<grid, 256, attn_smem>>>(qp, kcp, vcp, rap, ap);
    }

    sgemm_tf32_pipe<<<gg, gt, GEMM_SMEM_BYTES>>>(ap, wor, out, NTOK, DIM, DIM);
}

// round 9
// speedup vs baseline: 1.5717x; 1.5717x over previous
#include <cuda_runtime.h>
#include <cuda_bf16.h>
#include <math.h>

#define DIM     4096
#define NHEADS  32
#define HD      128
#define BSZ     8
#define SEQ     512
#define START_P 512
#define KVLEN   1024
#define NTOK    (BSZ*SEQ)   /* 4096 tokens */
#define MAXSEQ  2048

// Scratch (device globals; no runtime allocation allowed)
__device__ float g_q[(size_t)NTOK * DIM];
__device__ float g_k[(size_t)NTOK * DIM];
__device__ float g_v[(size_t)NTOK * DIM];
__device__ float g_attn[(size_t)NTOK * DIM];
// tf32-pre-rounded operands
__device__ float g_xr[(size_t)NTOK * DIM];
__device__ float g_wqr[(size_t)DIM * DIM];
__device__ float g_wkr[(size_t)DIM * DIM];
__device__ float g_wvr[(size_t)DIM * DIM];
__device__ float g_wor[(size_t)DIM * DIM];
// merged + tf32-rounded K/V for attention, and router additive mask
__device__ float g_kc[(size_t)BSZ * NHEADS * KVLEN * HD];
__device__ float g_vc[(size_t)BSZ * NHEADS * KVLEN * HD];
__device__ float g_radd[(size_t)BSZ * KVLEN];

// ---------------------------------------------------------------------------
// TF32 / async helpers
// ---------------------------------------------------------------------------
__device__ __forceinline__ float tf32r(float x) {
    float y;
    asm("cvt.rna.tf32.f32 %0, %1;" : "=f"(y) : "f"(x));
    return y;
}

__device__ __forceinline__ void mma_tf32(float* c, const unsigned* a, const unsigned* b) {
    asm volatile(
        "mma.sync.aligned.m16n8k8.row.col.f32.tf32.tf32.f32 "
        "{%0,%1,%2,%3}, {%4,%5,%6,%7}, {%8,%9}, {%0,%1,%2,%3};"
        : "+f"(c[0]), "+f"(c[1]), "+f"(c[2]), "+f"(c[3])
        : "r"(a[0]), "r"(a[1]), "r"(a[2]), "r"(a[3]),
          "r"(b[0]), "r"(b[1]));
}

__device__ __forceinline__ void cp_async16(float* smem_dst, const float* gsrc) {
    unsigned saddr = (unsigned)__cvta_generic_to_shared(smem_dst);
    asm volatile("cp.async.cg.shared.global [%0], [%1], 16;\n"
                 :: "r"(saddr), "l"(gsrc));
}
#define CP_COMMIT() asm volatile("cp.async.commit_group;\n" ::: "memory")
#define CP_WAIT1()  asm volatile("cp.async.wait_group 1;\n" ::: "memory")
#define CP_WAIT0()  asm volatile("cp.async.wait_group 0;\n" ::: "memory")

// ---------------------------------------------------------------------------
// Pre-round x and 4 weight matrices to tf32 (all are 4096x4096 fp32).
// ---------------------------------------------------------------------------
__global__ void round5_kernel(
    const float4* __restrict__ x,  const float4* __restrict__ wq,
    const float4* __restrict__ wk, const float4* __restrict__ wv,
    const float4* __restrict__ wo,
    float4* __restrict__ xr,  float4* __restrict__ wqr,
    float4* __restrict__ wkr, float4* __restrict__ wvr,
    float4* __restrict__ wor)
{
    size_t i = (size_t)blockIdx.x * blockDim.x + threadIdx.x;
    const size_t n = (size_t)DIM * DIM / 4;
    if (i >= n) return;
#define R4(dst, src) { float4 v = src[i]; \
    v.x = tf32r(v.x); v.y = tf32r(v.y); v.z = tf32r(v.z); v.w = tf32r(v.w); \
    dst[i] = v; }
    R4(xr, x) R4(wqr, wq) R4(wkr, wk) R4(wvr, wv) R4(wor, wo)
#undef R4
}

// ---------------------------------------------------------------------------
// TF32 tensor-core GEMM NT with cp.async 3-stage pipeline (unchanged).
// ---------------------------------------------------------------------------
#define GEMM_NSTAGE 3
#define GEMM_STAGE_FLOATS (2 * 128 * 32)
#define GEMM_SMEM_BYTES (GEMM_NSTAGE * GEMM_STAGE_FLOATS * 4)  /* 96 KB */

__global__ __launch_bounds__(256, 2) void sgemm_tf32_pipe(
    const float* __restrict__ A, const float* __restrict__ B,
    float* __restrict__ C, int M, int N, int K)
{
    extern __shared__ float sm[];
    const int tid = threadIdx.x;
    const int bm = blockIdx.y * 128;
    const int bn = blockIdx.x * 128;
    const int warp = tid >> 5, lane = tid & 31;
    const int wm = warp >> 2;
    const int wn = warp & 3;
    const int grp = lane >> 2;
    const int t4 = lane & 3;

    int pr[4], pc[4], poff[4];
#pragma unroll
    for (int p = 0; p < 4; p++) {
        int ci = tid + 256 * p;
        pr[p] = ci >> 3;
        pc[p] = ci & 7;
        poff[p] = (pr[p] << 5) + ((pc[p] ^ (pr[p] & 7)) << 2);
    }

    float acc[4][4][4];
#pragma unroll
    for (int mf = 0; mf < 4; mf++)
#pragma unroll
        for (int nf = 0; nf < 4; nf++)
#pragma unroll
            for (int r = 0; r < 4; r++) acc[mf][nf][r] = 0.f;

    const int KT = K / 32;

#pragma unroll
    for (int s = 0; s < 2; s++) {
        float* As = sm + s * GEMM_STAGE_FLOATS;
        float* Bs = As + 128 * 32;
        int k0 = s * 32;
#pragma unroll
        for (int p = 0; p < 4; p++) {
            cp_async16(As + poff[p], A + (size_t)(bm + pr[p]) * K + k0 + pc[p] * 4);
            cp_async16(Bs + poff[p], B + (size_t)(bn + pr[p]) * K + k0 + pc[p] * 4);
        }
        CP_COMMIT();
    }

    for (int kt = 0; kt < KT; kt++) {
        CP_WAIT1();
        __syncthreads();

        if (kt + 2 < KT) {
            int s = (kt + 2) % GEMM_NSTAGE;
            float* As = sm + s * GEMM_STAGE_FLOATS;
            float* Bs = As + 128 * 32;
            int k0 = (kt + 2) * 32;
#pragma unroll
            for (int p = 0; p < 4; p++) {
                cp_async16(As + poff[p], A + (size_t)(bm + pr[p]) * K + k0 + pc[p] * 4);
                cp_async16(Bs + poff[p], B + (size_t)(bn + pr[p]) * K + k0 + pc[p] * 4);
            }
        }
        CP_COMMIT();

        const float* As = sm + (kt % GEMM_NSTAGE) * GEMM_STAGE_FLOATS;
        const float* Bs = As + 128 * 32;

#pragma unroll
        for (int ks = 0; ks < 4; ks++) {
            const int ca = (2 * ks) ^ grp;
            const int cb = (2 * ks + 1) ^ grp;
            unsigned af[4][4], bf[4][2];
#pragma unroll
            for (int mf = 0; mf < 4; mf++) {
                int m0 = wm * 64 + mf * 16 + grp;
                af[mf][0] = __float_as_uint(As[m0 * 32 + ca * 4 + t4]);
                af[mf][1] = __float_as_uint(As[(m0 + 8) * 32 + ca * 4 + t4]);
                af[mf][2] = __float_as_uint(As[m0 * 32 + cb * 4 + t4]);
                af[mf][3] = __float_as_uint(As[(m0 + 8) * 32 + cb * 4 + t4]);
            }
#pragma unroll
            for (int nf = 0; nf < 4; nf++) {
                int n0 = wn * 32 + nf * 8 + grp;
                bf[nf][0] = __float_as_uint(Bs[n0 * 32 + ca * 4 + t4]);
                bf[nf][1] = __float_as_uint(Bs[n0 * 32 + cb * 4 + t4]);
            }
#pragma unroll
            for (int mf = 0; mf < 4; mf++)
#pragma unroll
                for (int nf = 0; nf < 4; nf++)
                    mma_tf32(acc[mf][nf], af[mf], bf[nf]);
        }
        __syncthreads();
    }

#pragma unroll
    for (int mf = 0; mf < 4; mf++) {
        int row0 = bm + wm * 64 + mf * 16 + grp;
#pragma unroll
        for (int nf = 0; nf < 4; nf++) {
            int col0 = bn + wn * 32 + nf * 8 + t4 * 2;
            float2 v0 = make_float2(acc[mf][nf][0], acc[mf][nf][1]);
            float2 v1 = make_float2(acc[mf][nf][2], acc[mf][nf][3]);
            *(float2*)(C + (size_t)row0 * N + col0) = v0;
            *(float2*)(C + (size_t)(row0 + 8) * N + col0) = v1;
        }
    }
}

// ---------------------------------------------------------------------------
// RoPE + scale + tf32-round Q in place.
// ---------------------------------------------------------------------------
__global__ void rope_q_kernel(float* __restrict__ q)
{
    int idx = blockIdx.x * blockDim.x + threadIdx.x;
    const int total = NTOK * NHEADS * 64;
    if (idx >= total) return;
    int i   = idx & 63;
    int rest = idx >> 6;
    int h   = rest & (NHEADS - 1);
    int tok = rest >> 5;
    int s   = tok & (SEQ - 1);
    float pos = (float)(START_P + s);
    const float scale = 0.08838834764831845f;

    float freq = exp2f(-(float)i * 0.20762050593045702f);
    float ang = pos * freq;
    float c = cosf(ang), sn = sinf(ang);

    size_t base = (size_t)tok * DIM + h * HD + i;
    float q0 = q[base], q1 = q[base + 64];
    q[base]      = tf32r((q0 * c - q1 * sn) * scale);
    q[base + 64] = tf32r((q1 * c + q0 * sn) * scale);
}

// ---------------------------------------------------------------------------
// Build merged tf32 K'/V' [b][h][1024][128] + router additive mask.
// ---------------------------------------------------------------------------
__global__ void prep_kv_kernel(
    const float* __restrict__ knew, const float* __restrict__ vnew,
    const float* __restrict__ cache_k, const float* __restrict__ cache_v,
    const float* __restrict__ router,
    float* __restrict__ kc, float* __restrict__ vc, float* __restrict__ radd)
{
    int idx = blockIdx.x * blockDim.x + threadIdx.x;
    const int total = BSZ * NHEADS * KVLEN * 64;
    if (idx >= total) return;
    int i   = idx & 63;
    int pos = (idx >> 6) & (KVLEN - 1);
    int h   = (idx >> 16) & (NHEADS - 1);
    int b   = idx >> 21;

    size_t dst = (((size_t)(b * NHEADS + h)) * KVLEN + pos) * HD + i;
    if (pos < START_P) {
        size_t src = (((size_t)(b * NHEADS + h)) * MAXSEQ + pos) * HD + i;
        kc[dst]      = tf32r(cache_k[src]);
        kc[dst + 64] = tf32r(cache_k[src + 64]);
        vc[dst]      = tf32r(cache_v[src]);
        vc[dst + 64] = tf32r(cache_v[src + 64]);
    } else {
        int s = pos - START_P;
        size_t src = ((size_t)(b * SEQ + s)) * DIM + h * HD + i;
        float freq = exp2f(-(float)i * 0.20762050593045702f);
        float ang = (float)pos * freq;
        float c = cosf(ang), sn = sinf(ang);
        float k0 = knew[src], k1 = knew[src + 64];
        kc[dst]      = tf32r(k0 * c - k1 * sn);
        kc[dst + 64] = tf32r(k1 * c + k0 * sn);
        vc[dst]      = tf32r(vnew[src]);
        vc[dst + 64] = tf32r(vnew[src + 64]);
    }
    if (h == 0 && i == 0) {
        float add = 0.f;
        if (pos >= START_P &&
            router[((size_t)b * SEQ + (pos - START_P)) * 2] == 0.f) add = -1e9f;
        radd[(size_t)b * KVLEN + pos] = add;
    }
}

// ---------------------------------------------------------------------------
// Tensor-core flash attention v3.
// Footprint 103.5 KB -> 2 blocks/SM (16 warps). KV tile = 32 rows; separate
// single K and V buffers with alternating cp.async groups:
//   wait K -> sync -> issue V(kt) -> S-mma+softmax -> wait V -> sync ->
//   issue K(kt+1) -> PV
// so each load hides behind half a tile of compute.
// Q/K stride 132 (banks 4*grp+t4), V stride 136 (banks 8*t4+grp): all
// fragment patterns conflict-free.
// ---------------------------------------------------------------------------
#define AQ_ST  132
#define AK_ST  132
#define AV_ST  136
#define KVT    32                     /* kv rows per tile */
#define AQ_FLOATS   (128 * AQ_ST)
#define AK_FLOATS   (KVT * AK_ST)
#define AV_FLOATS   (KVT * AV_ST)
#define ATTN_SMEM_FLOATS (AQ_FLOATS + AK_FLOATS + AV_FLOATS + KVLEN)

__global__ __launch_bounds__(256, 2) void attn_tc3_kernel(
    const float* __restrict__ qp, const float* __restrict__ kc,
    const float* __restrict__ vc, const float* __restrict__ radd_g,
    float* __restrict__ out)
{
    extern __shared__ float smem[];
    float* Qs = smem;
    float* Ks = smem + AQ_FLOATS;
    float* Vs = Ks + AK_FLOATS;
    float* radd_s = Vs + AV_FLOATS;   // [1024]

    const int qt = blockIdx.x;   // 0..3
    const int h  = blockIdx.y;
    const int b  = blockIdx.z;
    const int tid = threadIdx.x;
    const int wid = tid >> 5;
    const int lane = tid & 31;
    const int grp = lane >> 2;
    const int t4 = lane & 3;

    const float* qbase = qp + (size_t)(b * SEQ + qt * 128) * DIM + h * HD;
    const float* kbase = kc + ((size_t)(b * NHEADS + h)) * KVLEN * HD;
    const float* vbase = vc + ((size_t)(b * NHEADS + h)) * KVLEN * HD;

    // ---- prologue group: Q + radd + K(0) ----
#pragma unroll
    for (int p = 0; p < 16; p++) {
        int ci = tid + 256 * p;
        int r = ci >> 5, c = ci & 31;
        cp_async16(Qs + r * AQ_ST + c * 4, qbase + (size_t)r * DIM + c * 4);
    }
    cp_async16(radd_s + tid * 4, radd_g + (size_t)b * KVLEN + tid * 4);
#pragma unroll
    for (int p = 0; p < 4; p++) {
        int ci = tid + 256 * p;
        int r = ci >> 5, c = ci & 31;
        cp_async16(Ks + r * AK_ST + c * 4, kbase + (size_t)r * HD + c * 4);
    }
    CP_COMMIT();

    float Oc[16][4];
#pragma unroll
    for (int nf = 0; nf < 16; nf++)
#pragma unroll
        for (int r = 0; r < 4; r++) Oc[nf][r] = 0.f;

    float mrun0 = -1e30f, mrun1 = -1e30f, lrun0 = 0.f, lrun1 = 0.f;
    const int m0 = wid * 16;
    const int qpos0 = START_P + qt * 128 + m0 + grp;
    const int qpos1 = qpos0 + 8;
    const int srcA = (lane & ~3) | (t4 >> 1);
    const int srcB = srcA + 2;

    for (int kt = 0; kt < KVLEN / KVT; kt++) {
        // -- wait K(kt) (issued during PV of kt-1), then free V buffer --
        CP_WAIT0();
        __syncthreads();

        // -- issue V(kt): overlaps S + softmax --
#pragma unroll
        for (int p = 0; p < 4; p++) {
            int ci = tid + 256 * p;
            int r = ci >> 5, c = ci & 31;
            cp_async16(Vs + r * AV_ST + c * 4,
                       vbase + (size_t)(kt * KVT + r) * HD + c * 4);
        }
        CP_COMMIT();

        // ---- S = Q K^T (warp: 16 x 32, k=128) ----
        float sc[4][4];
#pragma unroll
        for (int nf = 0; nf < 4; nf++)
#pragma unroll
            for (int r = 0; r < 4; r++) sc[nf][r] = 0.f;

#pragma unroll
        for (int ks = 0; ks < 16; ks++) {
            int ko = ks * 8;
            unsigned a[4];
            a[0] = __float_as_uint(Qs[(m0 + grp) * AQ_ST + ko + t4]);
            a[1] = __float_as_uint(Qs[(m0 + grp + 8) * AQ_ST + ko + t4]);
            a[2] = __float_as_uint(Qs[(m0 + grp) * AQ_ST + ko + t4 + 4]);
            a[3] = __float_as_uint(Qs[(m0 + grp + 8) * AQ_ST + ko + t4 + 4]);
#pragma unroll
            for (int nf = 0; nf < 4; nf++) {
                unsigned bb[2];
                bb[0] = __float_as_uint(Ks[(8 * nf + grp) * AK_ST + ko + t4]);
                bb[1] = __float_as_uint(Ks[(8 * nf + grp) * AK_ST + ko + t4 + 4]);
                mma_tf32(sc[nf], a, bb);
            }
        }

        // ---- mask + online softmax ----
        float rmax0 = -1e30f, rmax1 = -1e30f;
#pragma unroll
        for (int nf = 0; nf < 4; nf++) {
#pragma unroll
            for (int e = 0; e < 2; e++) {
                int col = 8 * nf + 2 * t4 + e;
                int ng = kt * KVT + col;
                float add = radd_s[kt * KVT + col];
                float v0 = sc[nf][e]     + add + ((ng > qpos0) ? -1e9f : 0.f);
                float v1 = sc[nf][2 + e] + add + ((ng > qpos1) ? -1e9f : 0.f);
                sc[nf][e] = v0; sc[nf][2 + e] = v1;
                rmax0 = fmaxf(rmax0, v0);
                rmax1 = fmaxf(rmax1, v1);
            }
        }
        rmax0 = fmaxf(rmax0, __shfl_xor_sync(0xffffffffu, rmax0, 1));
        rmax0 = fmaxf(rmax0, __shfl_xor_sync(0xffffffffu, rmax0, 2));
        rmax1 = fmaxf(rmax1, __shfl_xor_sync(0xffffffffu, rmax1, 1));
        rmax1 = fmaxf(rmax1, __shfl_xor_sync(0xffffffffu, rmax1, 2));

        float mnew0 = fmaxf(mrun0, rmax0);
        float mnew1 = fmaxf(mrun1, rmax1);
        float alpha0 = __expf(mrun0 - mnew0);
        float alpha1 = __expf(mrun1 - mnew1);
        mrun0 = mnew0; mrun1 = mnew1;

        float ps0 = 0.f, ps1 = 0.f;
#pragma unroll
        for (int nf = 0; nf < 4; nf++) {
#pragma unroll
            for (int e = 0; e < 2; e++) {
                float p0 = __expf(sc[nf][e] - mnew0);
                float p1 = __expf(sc[nf][2 + e] - mnew1);
                ps0 += p0; ps1 += p1;
                sc[nf][e] = tf32r(p0);
                sc[nf][2 + e] = tf32r(p1);
            }
        }
        ps0 += __shfl_xor_sync(0xffffffffu, ps0, 1);
        ps0 += __shfl_xor_sync(0xffffffffu, ps0, 2);
        ps1 += __shfl_xor_sync(0xffffffffu, ps1, 1);
        ps1 += __shfl_xor_sync(0xffffffffu, ps1, 2);
        lrun0 = lrun0 * alpha0 + ps0;
        lrun1 = lrun1 * alpha1 + ps1;

#pragma unroll
        for (int nf = 0; nf < 16; nf++) {
            Oc[nf][0] *= alpha0; Oc[nf][1] *= alpha0;
            Oc[nf][2] *= alpha1; Oc[nf][3] *= alpha1;
        }

        // -- wait V(kt); free K buffer --
        CP_WAIT0();
        __syncthreads();

        // -- issue K(kt+1): overlaps PV --
        if (kt + 1 < KVLEN / KVT) {
#pragma unroll
            for (int p = 0; p < 4; p++) {
                int ci = tid + 256 * p;
                int r = ci >> 5, c = ci & 31;
                cp_async16(Ks + r * AK_ST + c * 4,
                           kbase + (size_t)((kt + 1) * KVT + r) * HD + c * 4);
            }
        }
        CP_COMMIT();

        // ---- O += P V  (P a-frags via quad shuffle from c-layout) ----
#pragma unroll
        for (int kcc = 0; kcc < 4; kcc++) {
            float x0 = __shfl_sync(0xffffffffu, sc[kcc][0], srcA);
            float x1 = __shfl_sync(0xffffffffu, sc[kcc][1], srcA);
            float y0 = __shfl_sync(0xffffffffu, sc[kcc][2], srcA);
            float y1 = __shfl_sync(0xffffffffu, sc[kcc][3], srcA);
            float x0b = __shfl_sync(0xffffffffu, sc[kcc][0], srcB);
            float x1b = __shfl_sync(0xffffffffu, sc[kcc][1], srcB);
            float y0b = __shfl_sync(0xffffffffu, sc[kcc][2], srcB);
            float y1b = __shfl_sync(0xffffffffu, sc[kcc][3], srcB);
            unsigned a[4];
            bool oddc = (t4 & 1);
            a[0] = __float_as_uint(oddc ? x1 : x0);
            a[1] = __float_as_uint(oddc ? y1 : y0);
            a[2] = __float_as_uint(oddc ? x1b : x0b);
            a[3] = __float_as_uint(oddc ? y1b : y0b);
            int ko = kcc * 8;
#pragma unroll
            for (int nf = 0; nf < 16; nf++) {
                unsigned bb[2];
                bb[0] = __float_as_uint(Vs[(ko + t4) * AV_ST + 8 * nf + grp]);
                bb[1] = __float_as_uint(Vs[(ko + t4 + 4) * AV_ST + 8 * nf + grp]);
                mma_tf32(Oc[nf], a, bb);
            }
        }
    }

    // ---- normalize + store (tf32-rounded: feeds WO GEMM) ----
    float inv0 = 1.f / lrun0;
    float inv1 = 1.f / lrun1;
    int tok0 = b * SEQ + qt * 128 + m0 + grp;
#pragma unroll
    for (int nf = 0; nf < 16; nf++) {
        int col = h * HD + 8 * nf + 2 * t4;
        float2 v0 = make_float2(tf32r(Oc[nf][0] * inv0), tf32r(Oc[nf][1] * inv0));
        float2 v1 = make_float2(tf32r(Oc[nf][2] * inv1), tf32r(Oc[nf][3] * inv1));
        *(float2*)(out + (size_t)tok0 * DIM + col) = v0;
        *(float2*)(out + (size_t)(tok0 + 8) * DIM + col) = v1;
    }
}

// ---------------------------------------------------------------------------
extern "C" void kernel_launch(void* const* d_in, const int* in_sizes, int n_in,
                              void* d_out, int out_size)
{
    const float* x       = (const float*)d_in[0];
    const float* router  = (const float*)d_in[1];
    const float* cache_k = (const float*)d_in[2];
    const float* cache_v = (const float*)d_in[3];
    const float* wq      = (const float*)d_in[6];
    const float* wk      = (const float*)d_in[7];
    const float* wv      = (const float*)d_in[8];
    const float* wo      = (const float*)d_in[9];
    float* out = (float*)d_out;

    float *qp, *kp, *vp, *ap, *xr, *wqr, *wkr, *wvr, *wor, *kcp, *vcp, *rap;
    cudaGetSymbolAddress((void**)&qp, g_q);
    cudaGetSymbolAddress((void**)&kp, g_k);
    cudaGetSymbolAddress((void**)&vp, g_v);
    cudaGetSymbolAddress((void**)&ap, g_attn);
    cudaGetSymbolAddress((void**)&xr, g_xr);
    cudaGetSymbolAddress((void**)&wqr, g_wqr);
    cudaGetSymbolAddress((void**)&wkr, g_wkr);
    cudaGetSymbolAddress((void**)&wvr, g_wvr);
    cudaGetSymbolAddress((void**)&wor, g_wor);
    cudaGetSymbolAddress((void**)&kcp, g_kc);
    cudaGetSymbolAddress((void**)&vcp, g_vc);
    cudaGetSymbolAddress((void**)&rap, g_radd);

    const int attn_smem = ATTN_SMEM_FLOATS * sizeof(float);   // ~103.5 KB
    cudaFuncSetAttribute(attn_tc3_kernel, cudaFuncAttributeMaxDynamicSharedMemorySize,
                         attn_smem);
    cudaFuncSetAttribute(sgemm_tf32_pipe, cudaFuncAttributeMaxDynamicSharedMemorySize,
                         GEMM_SMEM_BYTES);

    // pre-round x + weights to tf32
    {
        size_t n4 = (size_t)DIM * DIM / 4;
        int blocks = (int)((n4 + 255) / 256);
        round5_kernel<<<blocks, 256>>>(
            (const float4*)x, (const float4*)wq, (const float4*)wk,
            (const float4*)wv, (const float4*)wo,
            (float4*)xr, (float4*)wqr, (float4*)wkr, (float4*)wvr, (float4*)wor);
    }

    dim3 gg(DIM / 128, NTOK / 128), gt(256);
    sgemm_tf32_pipe<<<gg, gt, GEMM_SMEM_BYTES>>>(xr, wqr, qp, NTOK, DIM, DIM);
    sgemm_tf32_pipe<<<gg, gt, GEMM_SMEM_BYTES>>>(xr, wkr, kp, NTOK, DIM, DIM);
    sgemm_tf32_pipe<<<gg, gt, GEMM_SMEM_BYTES>>>(xr, wvr, vp, NTOK, DIM, DIM);

    // Q: rope+scale+tf32 in place
    {
        int total = NTOK * NHEADS * 64;
        rope_q_kernel<<<(total + 255) / 256, 256>>>(qp);
    }
    // K'/V' merge + rope + tf32, router mask
    {
        int total = BSZ * NHEADS * KVLEN * 64;
        prep_kv_kernel<<<(total + 255) / 256, 256>>>(
            kp, vp, cache_k, cache_v, router, kcp, vcp, rap);
    }

    {
        dim3 grid(SEQ / 128, NHEADS, BSZ);
        attn_tc3_kernel<<<grid, 256, attn_smem>>>(qp, kcp, vcp, rap, ap);
    }

    sgemm_tf32_pipe<<<gg, gt, GEMM_SMEM_BYTES>>>(ap, wor, out, NTOK, DIM, DIM);
}

// round 12
// speedup vs baseline: 1.6294x; 1.0367x over previous
#include <cuda_runtime.h>
#include <cuda_bf16.h>
#include <math.h>

#define DIM     4096
#define NHEADS  32
#define HD      128
#define BSZ     8
#define SEQ     512
#define START_P 512
#define KVLEN   1024
#define NTOK    (BSZ*SEQ)   /* 4096 tokens */
#define MAXSEQ  2048

// Scratch (device globals; no runtime allocation allowed)
__device__ float g_q[(size_t)NTOK * DIM];
__device__ float g_k[(size_t)NTOK * DIM];
__device__ float g_v[(size_t)NTOK * DIM];
__device__ float g_attn[(size_t)NTOK * DIM];
// tf32-pre-rounded operands
__device__ float g_xr[(size_t)NTOK * DIM];
__device__ float g_wqr[(size_t)DIM * DIM];
__device__ float g_wkr[(size_t)DIM * DIM];
__device__ float g_wvr[(size_t)DIM * DIM];
__device__ float g_wor[(size_t)DIM * DIM];
// merged + tf32-rounded K/V for attention, and router additive mask
__device__ float g_kc[(size_t)BSZ * NHEADS * KVLEN * HD];
__device__ float g_vc[(size_t)BSZ * NHEADS * KVLEN * HD];
__device__ float g_radd[(size_t)BSZ * KVLEN];

// ---------------------------------------------------------------------------
// TF32 / async helpers
// ---------------------------------------------------------------------------
__device__ __forceinline__ float tf32r(float x) {
    float y;
    asm("cvt.rna.tf32.f32 %0, %1;" : "=f"(y) : "f"(x));
    return y;
}

__device__ __forceinline__ void mma_tf32(float* c, const unsigned* a, const unsigned* b) {
    asm volatile(
        "mma.sync.aligned.m16n8k8.row.col.f32.tf32.tf32.f32 "
        "{%0,%1,%2,%3}, {%4,%5,%6,%7}, {%8,%9}, {%0,%1,%2,%3};"
        : "+f"(c[0]), "+f"(c[1]), "+f"(c[2]), "+f"(c[3])
        : "r"(a[0]), "r"(a[1]), "r"(a[2]), "r"(a[3]),
          "r"(b[0]), "r"(b[1]));
}

__device__ __forceinline__ void cp_async16(float* smem_dst, const float* gsrc) {
    unsigned saddr = (unsigned)__cvta_generic_to_shared(smem_dst);
    asm volatile("cp.async.cg.shared.global [%0], [%1], 16;\n"
                 :: "r"(saddr), "l"(gsrc));
}
#define CP_COMMIT() asm volatile("cp.async.commit_group;\n" ::: "memory")
#define CP_WAIT1()  asm volatile("cp.async.wait_group 1;\n" ::: "memory")
#define CP_WAIT0()  asm volatile("cp.async.wait_group 0;\n" ::: "memory")

// ---------------------------------------------------------------------------
// Pre-round x and 4 weight matrices to tf32 (all are 4096x4096 fp32).
// ---------------------------------------------------------------------------
__global__ void round5_kernel(
    const float4* __restrict__ x,  const float4* __restrict__ wq,
    const float4* __restrict__ wk, const float4* __restrict__ wv,
    const float4* __restrict__ wo,
    float4* __restrict__ xr,  float4* __restrict__ wqr,
    float4* __restrict__ wkr, float4* __restrict__ wvr,
    float4* __restrict__ wor)
{
    size_t i = (size_t)blockIdx.x * blockDim.x + threadIdx.x;
    const size_t n = (size_t)DIM * DIM / 4;
    if (i >= n) return;
#define R4(dst, src) { float4 v = src[i]; \
    v.x = tf32r(v.x); v.y = tf32r(v.y); v.z = tf32r(v.z); v.w = tf32r(v.w); \
    dst[i] = v; }
    R4(xr, x) R4(wqr, wq) R4(wkr, wk) R4(wvr, wv) R4(wor, wo)
#undef R4
}

// ---------------------------------------------------------------------------
// TF32 tensor-core GEMM NT with cp.async 3-stage pipeline.
// Scheduling (vs R9): (1) single __syncthreads per k-tile — the top barrier
// already proves the refill-target stage is free; (2) cp.async issue moved
// AFTER the mma loop so tensor work starts immediately at the barrier.
// Commit-group count per iteration unchanged -> WAIT1 still resolves tile kt.
// ---------------------------------------------------------------------------
#define GEMM_NSTAGE 3
#define GEMM_STAGE_FLOATS (2 * 128 * 32)
#define GEMM_SMEM_BYTES (GEMM_NSTAGE * GEMM_STAGE_FLOATS * 4)  /* 96 KB */

__global__ __launch_bounds__(256, 2) void sgemm_tf32_pipe(
    const float* __restrict__ A, const float* __restrict__ B,
    float* __restrict__ C, int M, int N, int K)
{
    extern __shared__ float sm[];
    const int tid = threadIdx.x;
    const int bm = blockIdx.y * 128;
    const int bn = blockIdx.x * 128;
    const int warp = tid >> 5, lane = tid & 31;
    const int wm = warp >> 2;
    const int wn = warp & 3;
    const int grp = lane >> 2;
    const int t4 = lane & 3;

    int pr[4], pc[4], poff[4];
#pragma unroll
    for (int p = 0; p < 4; p++) {
        int ci = tid + 256 * p;
        pr[p] = ci >> 3;
        pc[p] = ci & 7;
        poff[p] = (pr[p] << 5) + ((pc[p] ^ (pr[p] & 7)) << 2);
    }

    float acc[4][4][4];
#pragma unroll
    for (int mf = 0; mf < 4; mf++)
#pragma unroll
        for (int nf = 0; nf < 4; nf++)
#pragma unroll
            for (int r = 0; r < 4; r++) acc[mf][nf][r] = 0.f;

    const int KT = K / 32;

    // prologue: issue stages 0,1
#pragma unroll
    for (int s = 0; s < 2; s++) {
        float* As = sm + s * GEMM_STAGE_FLOATS;
        float* Bs = As + 128 * 32;
        int k0 = s * 32;
#pragma unroll
        for (int p = 0; p < 4; p++) {
            cp_async16(As + poff[p], A + (size_t)(bm + pr[p]) * K + k0 + pc[p] * 4);
            cp_async16(Bs + poff[p], B + (size_t)(bn + pr[p]) * K + k0 + pc[p] * 4);
        }
        CP_COMMIT();
    }

    for (int kt = 0; kt < KT; kt++) {
        CP_WAIT1();            // tile kt resident
        __syncthreads();       // sole barrier: also proves stage (kt-1)%3 free

        const float* As = sm + (kt % GEMM_NSTAGE) * GEMM_STAGE_FLOATS;
        const float* Bs = As + 128 * 32;

#pragma unroll
        for (int ks = 0; ks < 4; ks++) {
            const int ca = (2 * ks) ^ grp;
            const int cb = (2 * ks + 1) ^ grp;
            unsigned af[4][4], bf[4][2];
#pragma unroll
            for (int mf = 0; mf < 4; mf++) {
                int m0 = wm * 64 + mf * 16 + grp;
                af[mf][0] = __float_as_uint(As[m0 * 32 + ca * 4 + t4]);
                af[mf][1] = __float_as_uint(As[(m0 + 8) * 32 + ca * 4 + t4]);
                af[mf][2] = __float_as_uint(As[m0 * 32 + cb * 4 + t4]);
                af[mf][3] = __float_as_uint(As[(m0 + 8) * 32 + cb * 4 + t4]);
            }
#pragma unroll
            for (int nf = 0; nf < 4; nf++) {
                int n0 = wn * 32 + nf * 8 + grp;
                bf[nf][0] = __float_as_uint(Bs[n0 * 32 + ca * 4 + t4]);
                bf[nf][1] = __float_as_uint(Bs[n0 * 32 + cb * 4 + t4]);
            }
#pragma unroll
            for (int mf = 0; mf < 4; mf++)
#pragma unroll
                for (int nf = 0; nf < 4; nf++)
                    mma_tf32(acc[mf][nf], af[mf], bf[nf]);
        }

        // refill stage (kt+2)%3 = (kt-1)%3 (freed by the barrier above)
        if (kt + 2 < KT) {
            int s = (kt + 2) % GEMM_NSTAGE;
            float* Asw = sm + s * GEMM_STAGE_FLOATS;
            float* Bsw = Asw + 128 * 32;
            int k0 = (kt + 2) * 32;
#pragma unroll
            for (int p = 0; p < 4; p++) {
                cp_async16(Asw + poff[p], A + (size_t)(bm + pr[p]) * K + k0 + pc[p] * 4);
                cp_async16(Bsw + poff[p], B + (size_t)(bn + pr[p]) * K + k0 + pc[p] * 4);
            }
        }
        CP_COMMIT();   // uniform group count (possibly empty)
    }

    // epilogue
#pragma unroll
    for (int mf = 0; mf < 4; mf++) {
        int row0 = bm + wm * 64 + mf * 16 + grp;
#pragma unroll
        for (int nf = 0; nf < 4; nf++) {
            int col0 = bn + wn * 32 + nf * 8 + t4 * 2;
            float2 v0 = make_float2(acc[mf][nf][0], acc[mf][nf][1]);
            float2 v1 = make_float2(acc[mf][nf][2], acc[mf][nf][3]);
            *(float2*)(C + (size_t)row0 * N + col0) = v0;
            *(float2*)(C + (size_t)(row0 + 8) * N + col0) = v1;
        }
    }
}

// ---------------------------------------------------------------------------
// RoPE + scale + tf32-round Q in place.
// ---------------------------------------------------------------------------
__global__ void rope_q_kernel(float* __restrict__ q)
{
    int idx = blockIdx.x * blockDim.x + threadIdx.x;
    const int total = NTOK * NHEADS * 64;
    if (idx >= total) return;
    int i   = idx & 63;
    int rest = idx >> 6;
    int h   = rest & (NHEADS - 1);
    int tok = rest >> 5;
    int s   = tok & (SEQ - 1);
    float pos = (float)(START_P + s);
    const float scale = 0.08838834764831845f;

    float freq = exp2f(-(float)i * 0.20762050593045702f);
    float ang = pos * freq;
    float c = cosf(ang), sn = sinf(ang);

    size_t base = (size_t)tok * DIM + h * HD + i;
    float q0 = q[base], q1 = q[base + 64];
    q[base]      = tf32r((q0 * c - q1 * sn) * scale);
    q[base + 64] = tf32r((q1 * c + q0 * sn) * scale);
}

// ---------------------------------------------------------------------------
// Build merged tf32 K'/V' [b][h][1024][128] + router additive mask.
// ---------------------------------------------------------------------------
__global__ void prep_kv_kernel(
    const float* __restrict__ knew, const float* __restrict__ vnew,
    const float* __restrict__ cache_k, const float* __restrict__ cache_v,
    const float* __restrict__ router,
    float* __restrict__ kc, float* __restrict__ vc, float* __restrict__ radd)
{
    int idx = blockIdx.x * blockDim.x + threadIdx.x;
    const int total = BSZ * NHEADS * KVLEN * 64;
    if (idx >= total) return;
    int i   = idx & 63;
    int pos = (idx >> 6) & (KVLEN - 1);
    int h   = (idx >> 16) & (NHEADS - 1);
    int b   = idx >> 21;

    size_t dst = (((size_t)(b * NHEADS + h)) * KVLEN + pos) * HD + i;
    if (pos < START_P) {
        size_t src = (((size_t)(b * NHEADS + h)) * MAXSEQ + pos) * HD + i;
        kc[dst]      = tf32r(cache_k[src]);
        kc[dst + 64] = tf32r(cache_k[src + 64]);
        vc[dst]      = tf32r(cache_v[src]);
        vc[dst + 64] = tf32r(cache_v[src + 64]);
    } else {
        int s = pos - START_P;
        size_t src = ((size_t)(b * SEQ + s)) * DIM + h * HD + i;
        float freq = exp2f(-(float)i * 0.20762050593045702f);
        float ang = (float)pos * freq;
        float c = cosf(ang), sn = sinf(ang);
        float k0 = knew[src], k1 = knew[src + 64];
        kc[dst]      = tf32r(k0 * c - k1 * sn);
        kc[dst + 64] = tf32r(k1 * c + k0 * sn);
        vc[dst]      = tf32r(vnew[src]);
        vc[dst + 64] = tf32r(vnew[src + 64]);
    }
    if (h == 0 && i == 0) {
        float add = 0.f;
        if (pos >= START_P &&
            router[((size_t)b * SEQ + (pos - START_P)) * 2] == 0.f) add = -1e9f;
        radd[(size_t)b * KVLEN + pos] = add;
    }
}

// ---------------------------------------------------------------------------
// Tensor-core flash attention v3 (unchanged from R9: 103.5 KB, 2 blocks/SM,
// alternating K/V cp.async groups).
// ---------------------------------------------------------------------------
#define AQ_ST  132
#define AK_ST  132
#define AV_ST  136
#define KVT    32
#define AQ_FLOATS   (128 * AQ_ST)
#define AK_FLOATS   (KVT * AK_ST)
#define AV_FLOATS   (KVT * AV_ST)
#define ATTN_SMEM_FLOATS (AQ_FLOATS + AK_FLOATS + AV_FLOATS + KVLEN)

__global__ __launch_bounds__(256, 2) void attn_tc3_kernel(
    const float* __restrict__ qp, const float* __restrict__ kc,
    const float* __restrict__ vc, const float* __restrict__ radd_g,
    float* __restrict__ out)
{
    extern __shared__ float smem[];
    float* Qs = smem;
    float* Ks = smem + AQ_FLOATS;
    float* Vs = Ks + AK_FLOATS;
    float* radd_s = Vs + AV_FLOATS;

    const int qt = blockIdx.x;
    const int h  = blockIdx.y;
    const int b  = blockIdx.z;
    const int tid = threadIdx.x;
    const int wid = tid >> 5;
    const int lane = tid & 31;
    const int grp = lane >> 2;
    const int t4 = lane & 3;

    const float* qbase = qp + (size_t)(b * SEQ + qt * 128) * DIM + h * HD;
    const float* kbase = kc + ((size_t)(b * NHEADS + h)) * KVLEN * HD;
    const float* vbase = vc + ((size_t)(b * NHEADS + h)) * KVLEN * HD;

#pragma unroll
    for (int p = 0; p < 16; p++) {
        int ci = tid + 256 * p;
        int r = ci >> 5, c = ci & 31;
        cp_async16(Qs + r * AQ_ST + c * 4, qbase + (size_t)r * DIM + c * 4);
    }
    cp_async16(radd_s + tid * 4, radd_g + (size_t)b * KVLEN + tid * 4);
#pragma unroll
    for (int p = 0; p < 4; p++) {
        int ci = tid + 256 * p;
        int r = ci >> 5, c = ci & 31;
        cp_async16(Ks + r * AK_ST + c * 4, kbase + (size_t)r * HD + c * 4);
    }
    CP_COMMIT();

    float Oc[16][4];
#pragma unroll
    for (int nf = 0; nf < 16; nf++)
#pragma unroll
        for (int r = 0; r < 4; r++) Oc[nf][r] = 0.f;

    float mrun0 = -1e30f, mrun1 = -1e30f, lrun0 = 0.f, lrun1 = 0.f;
    const int m0 = wid * 16;
    const int qpos0 = START_P + qt * 128 + m0 + grp;
    const int qpos1 = qpos0 + 8;
    const int srcA = (lane & ~3) | (t4 >> 1);
    const int srcB = srcA + 2;

    for (int kt = 0; kt < KVLEN / KVT; kt++) {
        CP_WAIT0();
        __syncthreads();

#pragma unroll
        for (int p = 0; p < 4; p++) {
            int ci = tid + 256 * p;
            int r = ci >> 5, c = ci & 31;
            cp_async16(Vs + r * AV_ST + c * 4,
                       vbase + (size_t)(kt * KVT + r) * HD + c * 4);
        }
        CP_COMMIT();

        float sc[4][4];
#pragma unroll
        for (int nf = 0; nf < 4; nf++)
#pragma unroll
            for (int r = 0; r < 4; r++) sc[nf][r] = 0.f;

#pragma unroll
        for (int ks = 0; ks < 16; ks++) {
            int ko = ks * 8;
            unsigned a[4];
            a[0] = __float_as_uint(Qs[(m0 + grp) * AQ_ST + ko + t4]);
            a[1] = __float_as_uint(Qs[(m0 + grp + 8) * AQ_ST + ko + t4]);
            a[2] = __float_as_uint(Qs[(m0 + grp) * AQ_ST + ko + t4 + 4]);
            a[3] = __float_as_uint(Qs[(m0 + grp + 8) * AQ_ST + ko + t4 + 4]);
#pragma unroll
            for (int nf = 0; nf < 4; nf++) {
                unsigned bb[2];
                bb[0] = __float_as_uint(Ks[(8 * nf + grp) * AK_ST + ko + t4]);
                bb[1] = __float_as_uint(Ks[(8 * nf + grp) * AK_ST + ko + t4 + 4]);
                mma_tf32(sc[nf], a, bb);
            }
        }

        float rmax0 = -1e30f, rmax1 = -1e30f;
#pragma unroll
        for (int nf = 0; nf < 4; nf++) {
#pragma unroll
            for (int e = 0; e < 2; e++) {
                int col = 8 * nf + 2 * t4 + e;
                int ng = kt * KVT + col;
                float add = radd_s[kt * KVT + col];
                float v0 = sc[nf][e]     + add + ((ng > qpos0) ? -1e9f : 0.f);
                float v1 = sc[nf][2 + e] + add + ((ng > qpos1) ? -1e9f : 0.f);
                sc[nf][e] = v0; sc[nf][2 + e] = v1;
                rmax0 = fmaxf(rmax0, v0);
                rmax1 = fmaxf(rmax1, v1);
            }
        }
        rmax0 = fmaxf(rmax0, __shfl_xor_sync(0xffffffffu, rmax0, 1));
        rmax0 = fmaxf(rmax0, __shfl_xor_sync(0xffffffffu, rmax0, 2));
        rmax1 = fmaxf(rmax1, __shfl_xor_sync(0xffffffffu, rmax1, 1));
        rmax1 = fmaxf(rmax1, __shfl_xor_sync(0xffffffffu, rmax1, 2));

        float mnew0 = fmaxf(mrun0, rmax0);
        float mnew1 = fmaxf(mrun1, rmax1);
        float alpha0 = __expf(mrun0 - mnew0);
        float alpha1 = __expf(mrun1 - mnew1);
        mrun0 = mnew0; mrun1 = mnew1;

        float ps0 = 0.f, ps1 = 0.f;
#pragma unroll
        for (int nf = 0; nf < 4; nf++) {
#pragma unroll
            for (int e = 0; e < 2; e++) {
                float p0 = __expf(sc[nf][e] - mnew0);
                float p1 = __expf(sc[nf][2 + e] - mnew1);
                ps0 += p0; ps1 += p1;
                sc[nf][e] = tf32r(p0);
                sc[nf][2 + e] = tf32r(p1);
            }
        }
        ps0 += __shfl_xor_sync(0xffffffffu, ps0, 1);
        ps0 += __shfl_xor_sync(0xffffffffu, ps0, 2);
        ps1 += __shfl_xor_sync(0xffffffffu, ps1, 1);
        ps1 += __shfl_xor_sync(0xffffffffu, ps1, 2);
        lrun0 = lrun0 * alpha0 + ps0;
        lrun1 = lrun1 * alpha1 + ps1;

#pragma unroll
        for (int nf = 0; nf < 16; nf++) {
            Oc[nf][0] *= alpha0; Oc[nf][1] *= alpha0;
            Oc[nf][2] *= alpha1; Oc[nf][3] *= alpha1;
        }

        CP_WAIT0();
        __syncthreads();

        if (kt + 1 < KVLEN / KVT) {
#pragma unroll
            for (int p = 0; p < 4; p++) {
                int ci = tid + 256 * p;
                int r = ci >> 5, c = ci & 31;
                cp_async16(Ks + r * AK_ST + c * 4,
                           kbase + (size_t)((kt + 1) * KVT + r) * HD + c * 4);
            }
        }
        CP_COMMIT();

#pragma unroll
        for (int kcc = 0; kcc < 4; kcc++) {
            float x0 = __shfl_sync(0xffffffffu, sc[kcc][0], srcA);
            float x1 = __shfl_sync(0xffffffffu, sc[kcc][1], srcA);
            float y0 = __shfl_sync(0xffffffffu, sc[kcc][2], srcA);
            float y1 = __shfl_sync(0xffffffffu, sc[kcc][3], srcA);
            float x0b = __shfl_sync(0xffffffffu, sc[kcc][0], srcB);
            float x1b = __shfl_sync(0xffffffffu, sc[kcc][1], srcB);
            float y0b = __shfl_sync(0xffffffffu, sc[kcc][2], srcB);
            float y1b = __shfl_sync(0xffffffffu, sc[kcc][3], srcB);
            unsigned a[4];
            bool oddc = (t4 & 1);
            a[0] = __float_as_uint(oddc ? x1 : x0);
            a[1] = __float_as_uint(oddc ? y1 : y0);
            a[2] = __float_as_uint(oddc ? x1b : x0b);
            a[3] = __float_as_uint(oddc ? y1b : y0b);
            int ko = kcc * 8;
#pragma unroll
            for (int nf = 0; nf < 16; nf++) {
                unsigned bb[2];
                bb[0] = __float_as_uint(Vs[(ko + t4) * AV_ST + 8 * nf + grp]);
                bb[1] = __float_as_uint(Vs[(ko + t4 + 4) * AV_ST + 8 * nf + grp]);
                mma_tf32(Oc[nf], a, bb);
            }
        }
    }

    float inv0 = 1.f / lrun0;
    float inv1 = 1.f / lrun1;
    int tok0 = b * SEQ + qt * 128 + m0 + grp;
#pragma unroll
    for (int nf = 0; nf < 16; nf++) {
        int col = h * HD + 8 * nf + 2 * t4;
        float2 v0 = make_float2(tf32r(Oc[nf][0] * inv0), tf32r(Oc[nf][1] * inv0));
        float2 v1 = make_float2(tf32r(Oc[nf][2] * inv1), tf32r(Oc[nf][3] * inv1));
        *(float2*)(out + (size_t)tok0 * DIM + col) = v0;
        *(float2*)(out + (size_t)(tok0 + 8) * DIM + col) = v1;
    }
}

// ---------------------------------------------------------------------------
extern "C" void kernel_launch(void* const* d_in, const int* in_sizes, int n_in,
                              void* d_out, int out_size)
{
    const float* x       = (const float*)d_in[0];
    const float* router  = (const float*)d_in[1];
    const float* cache_k = (const float*)d_in[2];
    const float* cache_v = (const float*)d_in[3];
    const float* wq      = (const float*)d_in[6];
    const float* wk      = (const float*)d_in[7];
    const float* wv      = (const float*)d_in[8];
    const float* wo      = (const float*)d_in[9];
    float* out = (float*)d_out;

    float *qp, *kp, *vp, *ap, *xr, *wqr, *wkr, *wvr, *wor, *kcp, *vcp, *rap;
    cudaGetSymbolAddress((void**)&qp, g_q);
    cudaGetSymbolAddress((void**)&kp, g_k);
    cudaGetSymbolAddress((void**)&vp, g_v);
    cudaGetSymbolAddress((void**)&ap, g_attn);
    cudaGetSymbolAddress((void**)&xr, g_xr);
    cudaGetSymbolAddress((void**)&wqr, g_wqr);
    cudaGetSymbolAddress((void**)&wkr, g_wkr);
    cudaGetSymbolAddress((void**)&wvr, g_wvr);
    cudaGetSymbolAddress((void**)&wor, g_wor);
    cudaGetSymbolAddress((void**)&kcp, g_kc);
    cudaGetSymbolAddress((void**)&vcp, g_vc);
    cudaGetSymbolAddress((void**)&rap, g_radd);

    const int attn_smem = ATTN_SMEM_FLOATS * sizeof(float);
    cudaFuncSetAttribute(attn_tc3_kernel, cudaFuncAttributeMaxDynamicSharedMemorySize,
                         attn_smem);
    cudaFuncSetAttribute(sgemm_tf32_pipe, cudaFuncAttributeMaxDynamicSharedMemorySize,
                         GEMM_SMEM_BYTES);

    // pre-round x + weights to tf32
    {
        size_t n4 = (size_t)DIM * DIM / 4;
        int blocks = (int)((n4 + 255) / 256);
        round5_kernel<<<blocks, 256>>>(
            (const float4*)x, (const float4*)wq, (const float4*)wk,
            (const float4*)wv, (const float4*)wo,
            (float4*)xr, (float4*)wqr, (float4*)wkr, (float4*)wvr, (float4*)wor);
    }

    dim3 gg(DIM / 128, NTOK / 128), gt(256);
    sgemm_tf32_pipe<<<gg, gt, GEMM_SMEM_BYTES>>>(xr, wqr, qp, NTOK, DIM, DIM);
    sgemm_tf32_pipe<<<gg, gt, GEMM_SMEM_BYTES>>>(xr, wkr, kp, NTOK, DIM, DIM);
    sgemm_tf32_pipe<<<gg, gt, GEMM_SMEM_BYTES>>>(xr, wvr, vp, NTOK, DIM, DIM);

    // Q: rope+scale+tf32 in place
    {
        int total = NTOK * NHEADS * 64;
        rope_q_kernel<<<(total + 255) / 256, 256>>>(qp);
    }
    // K'/V' merge + rope + tf32, router mask
    {
        int total = BSZ * NHEADS * KVLEN * 64;
        prep_kv_kernel<<<(total + 255) / 256, 256>>>(
            kp, vp, cache_k, cache_v, router, kcp, vcp, rap);
    }

    {
        dim3 grid(SEQ / 128, NHEADS, BSZ);
        attn_tc3_kernel<<<grid, 256, attn_smem>>>(qp, kcp, vcp, rap, ap);
    }

    sgemm_tf32_pipe<<<gg, gt, GEMM_SMEM_BYTES>>>(ap, wor, out, NTOK, DIM, DIM);
}